// round 1
// baseline (speedup 1.0000x reference)
#include <cuda_runtime.h>
#include <cuda_bf16.h>
#include <math.h>

#define NN 50000
#define EE 800000
#define FF 128

// ---------------- scratch (static device globals; no allocation) ----------------
__device__ int   g_cnt[NN];
__device__ float g_dis[NN];
__device__ int   g_rowstart[NN + 1];
__device__ int   g_fillptr[NN];
__device__ int   g_csr[EE];
__device__ float g_bufA[(size_t)NN * FF];
__device__ float g_bufB[(size_t)NN * FF];

// ---------------- small helpers ----------------
__device__ __forceinline__ float4 ld4(const float* p) { return *(const float4*)p; }

// ---------------- CSR build ----------------
__global__ void zero_cnt_kernel() {
    int i = blockIdx.x * blockDim.x + threadIdx.x;
    if (i < NN) g_cnt[i] = 0;
}

__global__ void count_kernel(const int* __restrict__ dst) {
    int i = blockIdx.x * blockDim.x + threadIdx.x;
    if (i < EE) atomicAdd(&g_cnt[dst[i]], 1);
}

__global__ void dis_kernel() {
    int i = blockIdx.x * blockDim.x + threadIdx.x;
    if (i < NN) g_dis[i] = rsqrtf((float)g_cnt[i] + 1.0f);  // +1 self loop
}

// single-block exclusive scan over g_cnt -> g_rowstart / g_fillptr
__global__ void scan_kernel() {
    const int T = 1024;
    const int CHUNK = (NN + T - 1) / T;  // 49
    __shared__ int s_sums[T];
    int tid = threadIdx.x;
    int base = tid * CHUNK;
    int mysum = 0;
    for (int j = 0; j < CHUNK; j++) {
        int idx = base + j;
        if (idx < NN) mysum += g_cnt[idx];
    }
    s_sums[tid] = mysum;
    __syncthreads();
    // Hillis-Steele inclusive scan
    for (int off = 1; off < T; off <<= 1) {
        int add = (tid >= off) ? s_sums[tid - off] : 0;
        __syncthreads();
        s_sums[tid] += add;
        __syncthreads();
    }
    int running = s_sums[tid] - mysum;  // exclusive prefix
    for (int j = 0; j < CHUNK; j++) {
        int idx = base + j;
        if (idx < NN) {
            g_rowstart[idx] = running;
            g_fillptr[idx]  = running;
            running += g_cnt[idx];
        }
    }
    if (tid == 0) g_rowstart[NN] = EE;
}

__global__ void fill_kernel(const int* __restrict__ src, const int* __restrict__ dst) {
    int i = blockIdx.x * blockDim.x + threadIdx.x;
    if (i < EE) {
        int d = dst[i];
        int p = atomicAdd(&g_fillptr[d], 1);
        g_csr[p] = src[i];
    }
}

// ---------------- GEMM: C[M x 128] = A[M x 128] * B[128 x 128], fp32 ----------------
#define BM 128
#define BN 128
#define BK 32
__global__ __launch_bounds__(256, 2)
void gemm128_kernel(const float* __restrict__ A, const float* __restrict__ B,
                    float* __restrict__ C, int M) {
    __shared__ float As[BK][BM];  // [k][m]
    __shared__ float Bs[BK][BN];  // [k][n]
    int tid = threadIdx.x;                 // 256 threads
    int m0 = blockIdx.x * BM;

    float acc[8][8];
#pragma unroll
    for (int i = 0; i < 8; i++)
#pragma unroll
        for (int j = 0; j < 8; j++) acc[i][j] = 0.0f;

    int arow  = tid >> 3;          // 0..31
    int acol4 = (tid & 7) * 4;     // 0..28
    int brow  = tid >> 5;          // 0..7
    int bcol4 = (tid & 31) * 4;    // 0..124
    int ty = tid >> 4, tx = tid & 15;

    for (int k0 = 0; k0 < FF; k0 += BK) {
#pragma unroll
        for (int i = 0; i < 4; i++) {
            int r = arow + 32 * i;
            int gm = m0 + r;
            float4 v = (gm < M) ? ld4(A + (size_t)gm * FF + k0 + acol4)
                                : make_float4(0.f, 0.f, 0.f, 0.f);
            As[acol4 + 0][r] = v.x;
            As[acol4 + 1][r] = v.y;
            As[acol4 + 2][r] = v.z;
            As[acol4 + 3][r] = v.w;
        }
#pragma unroll
        for (int i = 0; i < 4; i++) {
            int kk = brow + 8 * i;
            *(float4*)&Bs[kk][bcol4] = ld4(B + (size_t)(k0 + kk) * FF + bcol4);
        }
        __syncthreads();

#pragma unroll
        for (int k = 0; k < BK; k++) {
            float a[8], b[8];
            *(float4*)(a)     = *(float4*)&As[k][ty * 8];
            *(float4*)(a + 4) = *(float4*)&As[k][ty * 8 + 4];
            *(float4*)(b)     = *(float4*)&Bs[k][tx * 8];
            *(float4*)(b + 4) = *(float4*)&Bs[k][tx * 8 + 4];
#pragma unroll
            for (int i = 0; i < 8; i++)
#pragma unroll
                for (int j = 0; j < 8; j++) acc[i][j] = fmaf(a[i], b[j], acc[i][j]);
        }
        __syncthreads();
    }

#pragma unroll
    for (int i = 0; i < 8; i++) {
        int gm = m0 + ty * 8 + i;
        if (gm < M) {
            float* cp = C + (size_t)gm * FF + tx * 8;
            *(float4*)(cp)     = make_float4(acc[i][0], acc[i][1], acc[i][2], acc[i][3]);
            *(float4*)(cp + 4) = make_float4(acc[i][4], acc[i][5], acc[i][6], acc[i][7]);
        }
    }
}

// ---------------- aggregation + bias + ELU (warp per node) ----------------
__device__ __forceinline__ float elu1(float v) { return v > 0.f ? v : expm1f(v); }

__global__ __launch_bounds__(256)
void agg_elu_kernel(const float* __restrict__ T, const float* __restrict__ bias,
                    float* __restrict__ Hout) {
    int warp = threadIdx.x >> 5;
    int lane = threadIdx.x & 31;
    int v = blockIdx.x * 8 + warp;
    if (v >= NN) return;
    int c = lane * 4;  // this lane's 4 features

    float disv = g_dis[v];
    float wself = disv * disv;
    float4 tv = ld4(T + (size_t)v * FF + c);
    float ax = tv.x * wself, ay = tv.y * wself, az = tv.z * wself, aw = tv.w * wself;

    int beg = g_rowstart[v];
    int end = g_rowstart[v + 1];
    int e = beg;
    for (; e + 4 <= end; e += 4) {
        int s0 = g_csr[e + 0], s1 = g_csr[e + 1], s2 = g_csr[e + 2], s3 = g_csr[e + 3];
        float w0 = g_dis[s0] * disv, w1 = g_dis[s1] * disv;
        float w2 = g_dis[s2] * disv, w3 = g_dis[s3] * disv;
        float4 f0 = ld4(T + (size_t)s0 * FF + c);
        float4 f1 = ld4(T + (size_t)s1 * FF + c);
        float4 f2 = ld4(T + (size_t)s2 * FF + c);
        float4 f3 = ld4(T + (size_t)s3 * FF + c);
        ax = fmaf(f0.x, w0, ax); ay = fmaf(f0.y, w0, ay); az = fmaf(f0.z, w0, az); aw = fmaf(f0.w, w0, aw);
        ax = fmaf(f1.x, w1, ax); ay = fmaf(f1.y, w1, ay); az = fmaf(f1.z, w1, az); aw = fmaf(f1.w, w1, aw);
        ax = fmaf(f2.x, w2, ax); ay = fmaf(f2.y, w2, ay); az = fmaf(f2.z, w2, az); aw = fmaf(f2.w, w2, aw);
        ax = fmaf(f3.x, w3, ax); ay = fmaf(f3.y, w3, ay); az = fmaf(f3.z, w3, az); aw = fmaf(f3.w, w3, aw);
    }
    for (; e < end; e++) {
        int s = g_csr[e];
        float w = g_dis[s] * disv;
        float4 f = ld4(T + (size_t)s * FF + c);
        ax = fmaf(f.x, w, ax); ay = fmaf(f.y, w, ay); az = fmaf(f.z, w, az); aw = fmaf(f.w, w, aw);
    }

    float4 b = ld4(bias + c);
    float4 o;
    o.x = elu1(ax + b.x);
    o.y = elu1(ay + b.y);
    o.z = elu1(az + b.z);
    o.w = elu1(aw + b.w);
    *(float4*)(Hout + (size_t)v * FF + c) = o;
}

// ---------------- final head: out[v] = dot(h[v], Wl) + bl ----------------
__global__ __launch_bounds__(256)
void head_kernel(const float* __restrict__ H, const float* __restrict__ Wl,
                 const float* __restrict__ bl, float* __restrict__ out) {
    int warp = threadIdx.x >> 5;
    int lane = threadIdx.x & 31;
    int v = blockIdx.x * 8 + warp;
    if (v >= NN) return;
    int c = lane * 4;
    float4 h = ld4(H + (size_t)v * FF + c);
    float4 w = ld4(Wl + c);
    float s = h.x * w.x + h.y * w.y + h.z * w.z + h.w * w.w;
#pragma unroll
    for (int off = 16; off > 0; off >>= 1) s += __shfl_down_sync(0xFFFFFFFFu, s, off);
    if (lane == 0) out[v] = s + bl[0];
}

// ---------------- launch ----------------
extern "C" void kernel_launch(void* const* d_in, const int* in_sizes, int n_in,
                              void* d_out, int out_size) {
    const float* x  = (const float*)d_in[0];   // [N,128]
    const float* Ws = (const float*)d_in[1];   // [3,128,128]
    const float* bs = (const float*)d_in[2];   // [3,128]
    const float* Wl = (const float*)d_in[3];   // [128,1]
    const float* bl = (const float*)d_in[4];   // [1]
    const int*   ei = (const int*)d_in[5];     // [2,E]
    const int* src = ei;
    const int* dst = ei + EE;
    float* out = (float*)d_out;

    float *bufA, *bufB;
    cudaGetSymbolAddress((void**)&bufA, g_bufA);
    cudaGetSymbolAddress((void**)&bufB, g_bufB);

    // CSR build
    zero_cnt_kernel<<<(NN + 255) / 256, 256>>>();
    count_kernel<<<(EE + 255) / 256, 256>>>(dst);
    dis_kernel<<<(NN + 255) / 256, 256>>>();
    scan_kernel<<<1, 1024>>>();
    fill_kernel<<<(EE + 255) / 256, 256>>>(src, dst);

    int gemm_grid = (NN + BM - 1) / BM;   // 391
    int node_grid = (NN + 7) / 8;

    // layer 0: x -> bufA (t) -> bufB (h)
    gemm128_kernel<<<gemm_grid, 256>>>(x, Ws + 0 * FF * FF, bufA, NN);
    agg_elu_kernel<<<node_grid, 256>>>(bufA, bs + 0 * FF, bufB);
    // layer 1
    gemm128_kernel<<<gemm_grid, 256>>>(bufB, Ws + 1 * FF * FF, bufA, NN);
    agg_elu_kernel<<<node_grid, 256>>>(bufA, bs + 1 * FF, bufB);
    // layer 2
    gemm128_kernel<<<gemm_grid, 256>>>(bufB, Ws + 2 * FF * FF, bufA, NN);
    agg_elu_kernel<<<node_grid, 256>>>(bufA, bs + 2 * FF, bufB);
    // head
    head_kernel<<<node_grid, 256>>>(bufB, Wl, bl, out);
}

// round 2
// speedup vs baseline: 1.2724x; 1.2724x over previous
#include <cuda_runtime.h>
#include <cuda_bf16.h>
#include <math.h>

#define NN 50000
#define EE 800000
#define FF 128

typedef unsigned long long u64;

// ---------------- scratch (static device globals; no allocation) ----------------
__device__ int   g_cnt[NN];
__device__ float g_dis[NN];
__device__ int   g_rowstart[NN + 1];
__device__ int   g_fillptr[NN];
__device__ int   g_csr[EE];
__device__ int   g_blocksum[256];
__device__ int   g_blockoff[256];
__device__ float g_bufA[(size_t)NN * FF];
__device__ float g_bufB[(size_t)NN * FF];

// ---------------- small helpers ----------------
__device__ __forceinline__ float4 ld4(const float* p) { return *(const float4*)p; }

__device__ __forceinline__ u64 ffma2(u64 a, u64 b, u64 c) {
    u64 d;
    asm("fma.rn.f32x2 %0, %1, %2, %3;" : "=l"(d) : "l"(a), "l"(b), "l"(c));
    return d;
}
__device__ __forceinline__ u64 pack2(float lo, float hi) {
    u64 d;
    asm("mov.b64 %0, {%1, %2};" : "=l"(d) : "f"(lo), "f"(hi));
    return d;
}
__device__ __forceinline__ void unpack2(u64 v, float& lo, float& hi) {
    asm("mov.b64 {%0, %1}, %2;" : "=f"(lo), "=f"(hi) : "l"(v));
}

// ---------------- CSR build ----------------
__global__ void zero_cnt_kernel() {
    int i = blockIdx.x * blockDim.x + threadIdx.x;
    if (i < NN) g_cnt[i] = 0;
}

__global__ void count_kernel(const int* __restrict__ dst) {
    int i = blockIdx.x * blockDim.x + threadIdx.x;
    if (i < EE) atomicAdd(&g_cnt[dst[i]], 1);
}

__global__ void dis_kernel() {
    int i = blockIdx.x * blockDim.x + threadIdx.x;
    if (i < NN) g_dis[i] = rsqrtf((float)g_cnt[i] + 1.0f);  // +1 self loop
}

// two-level scan: scan1 (per-block), scan2 (block sums), scan3 (apply offsets)
__device__ __forceinline__ int block_exclusive_scan_256(int val, int tid, int* total_out) {
    int lane = tid & 31, w = tid >> 5;
    int x = val;
#pragma unroll
    for (int off = 1; off < 32; off <<= 1) {
        int y = __shfl_up_sync(0xFFFFFFFFu, x, off);
        if (lane >= off) x += y;
    }
    __shared__ int ws[8];
    if (lane == 31) ws[w] = x;
    __syncthreads();
    __shared__ int wo[9];
    if (tid == 0) {
        int run = 0;
#pragma unroll
        for (int i = 0; i < 8; i++) { wo[i] = run; run += ws[i]; }
        wo[8] = run;
    }
    __syncthreads();
    *total_out = wo[8];
    return x - val + wo[w];  // exclusive within block
}

__global__ void scan1_kernel() {  // grid=196, block=256
    int b = blockIdx.x, t = threadIdx.x;
    int i = b * 256 + t;
    int val = (i < NN) ? g_cnt[i] : 0;
    int total;
    int excl = block_exclusive_scan_256(val, t, &total);
    if (i < NN) g_rowstart[i] = excl;  // partial (needs block offset)
    if (t == 0) g_blocksum[b] = total;
}

__global__ void scan2_kernel() {  // 1 block, 256 threads
    int t = threadIdx.x;
    int nb = (NN + 255) / 256;
    int val = (t < nb) ? g_blocksum[t] : 0;
    int total;
    int excl = block_exclusive_scan_256(val, t, &total);
    g_blockoff[t] = excl;
}

__global__ void scan3_kernel() {  // grid=196, block=256
    int b = blockIdx.x, t = threadIdx.x;
    int i = b * 256 + t;
    if (i < NN) {
        int rs = g_rowstart[i] + g_blockoff[b];
        g_rowstart[i] = rs;
        g_fillptr[i]  = rs;
    }
    if (i == 0) g_rowstart[NN] = EE;
}

__global__ void fill_kernel(const int* __restrict__ src, const int* __restrict__ dst) {
    int i = blockIdx.x * blockDim.x + threadIdx.x;
    if (i < EE) {
        int d = dst[i];
        int p = atomicAdd(&g_fillptr[d], 1);
        g_csr[p] = src[i];
    }
}

// ---------------- GEMM: C[M x 128] = A[M x 128] * B[128 x 128], fp32, FFMA2 ----------------
#define BM 128
#define BN 128
#define BK 32
__global__ __launch_bounds__(256, 2)
void gemm128_kernel(const float* __restrict__ A, const float* __restrict__ B,
                    float* __restrict__ C, int M) {
    __shared__ float As[BK][BM];  // [k][m] — m contiguous: rows pair naturally for f32x2
    __shared__ float Bs[BK][BN];  // [k][n]
    int tid = threadIdx.x;        // 256 threads
    int m0 = blockIdx.x * BM;

    // accumulator: 4 row-pairs x 8 cols, packed f32x2 (lo=row 2ii, hi=row 2ii+1)
    u64 accp[4][8];
#pragma unroll
    for (int i = 0; i < 4; i++)
#pragma unroll
        for (int j = 0; j < 8; j++) accp[i][j] = 0ull;

    int arow  = tid >> 3;          // 0..31
    int acol4 = (tid & 7) * 4;     // 0..28
    int brow  = tid >> 5;          // 0..7
    int bcol4 = (tid & 31) * 4;    // 0..124
    int ty = tid >> 4, tx = tid & 15;

    for (int k0 = 0; k0 < FF; k0 += BK) {
#pragma unroll
        for (int i = 0; i < 4; i++) {
            int r = arow + 32 * i;
            int gm = m0 + r;
            float4 v = (gm < M) ? ld4(A + (size_t)gm * FF + k0 + acol4)
                                : make_float4(0.f, 0.f, 0.f, 0.f);
            As[acol4 + 0][r] = v.x;
            As[acol4 + 1][r] = v.y;
            As[acol4 + 2][r] = v.z;
            As[acol4 + 3][r] = v.w;
        }
#pragma unroll
        for (int i = 0; i < 4; i++) {
            int kk = brow + 8 * i;
            *(float4*)&Bs[kk][bcol4] = ld4(B + (size_t)(k0 + kk) * FF + bcol4);
        }
        __syncthreads();

#pragma unroll
        for (int k = 0; k < BK; k++) {
            // a: 4 natural pairs (rows contiguous in As[k][.])
            const u64* arowp = (const u64*)&As[k][ty * 8];
            u64 ap0 = arowp[0], ap1 = arowp[1], ap2 = arowp[2], ap3 = arowp[3];
            // b: 8 scalars, dup-packed
            float b[8];
            *(float4*)(b)     = *(float4*)&Bs[k][tx * 8];
            *(float4*)(b + 4) = *(float4*)&Bs[k][tx * 8 + 4];
            u64 bd[8];
#pragma unroll
            for (int j = 0; j < 8; j++) bd[j] = pack2(b[j], b[j]);
#pragma unroll
            for (int j = 0; j < 8; j++) {
                accp[0][j] = ffma2(ap0, bd[j], accp[0][j]);
                accp[1][j] = ffma2(ap1, bd[j], accp[1][j]);
                accp[2][j] = ffma2(ap2, bd[j], accp[2][j]);
                accp[3][j] = ffma2(ap3, bd[j], accp[3][j]);
            }
        }
        __syncthreads();
    }

#pragma unroll
    for (int ii = 0; ii < 4; ii++) {
        float lo[8], hi[8];
#pragma unroll
        for (int j = 0; j < 8; j++) unpack2(accp[ii][j], lo[j], hi[j]);
        int gm = m0 + ty * 8 + 2 * ii;
        if (gm < M) {
            float* cp = C + (size_t)gm * FF + tx * 8;
            *(float4*)(cp)     = make_float4(lo[0], lo[1], lo[2], lo[3]);
            *(float4*)(cp + 4) = make_float4(lo[4], lo[5], lo[6], lo[7]);
        }
        if (gm + 1 < M) {
            float* cp = C + (size_t)(gm + 1) * FF + tx * 8;
            *(float4*)(cp)     = make_float4(hi[0], hi[1], hi[2], hi[3]);
            *(float4*)(cp + 4) = make_float4(hi[4], hi[5], hi[6], hi[7]);
        }
    }
}

// ---------------- aggregation + bias + ELU (warp per node) ----------------
__device__ __forceinline__ float elu1(float v) { return v > 0.f ? v : expm1f(v); }

__global__ __launch_bounds__(256)
void agg_elu_kernel(const float* __restrict__ T, const float* __restrict__ bias,
                    float* __restrict__ Hout) {
    int warp = threadIdx.x >> 5;
    int lane = threadIdx.x & 31;
    int v = blockIdx.x * 8 + warp;
    if (v >= NN) return;
    int c = lane * 4;  // this lane's 4 features

    float disv = g_dis[v];
    float wself = disv * disv;
    float4 tv = ld4(T + (size_t)v * FF + c);
    float ax = tv.x * wself, ay = tv.y * wself, az = tv.z * wself, aw = tv.w * wself;

    int beg = g_rowstart[v];
    int end = g_rowstart[v + 1];
    int e = beg;
    for (; e + 4 <= end; e += 4) {
        int s0 = g_csr[e + 0], s1 = g_csr[e + 1], s2 = g_csr[e + 2], s3 = g_csr[e + 3];
        float w0 = g_dis[s0] * disv, w1 = g_dis[s1] * disv;
        float w2 = g_dis[s2] * disv, w3 = g_dis[s3] * disv;
        float4 f0 = ld4(T + (size_t)s0 * FF + c);
        float4 f1 = ld4(T + (size_t)s1 * FF + c);
        float4 f2 = ld4(T + (size_t)s2 * FF + c);
        float4 f3 = ld4(T + (size_t)s3 * FF + c);
        ax = fmaf(f0.x, w0, ax); ay = fmaf(f0.y, w0, ay); az = fmaf(f0.z, w0, az); aw = fmaf(f0.w, w0, aw);
        ax = fmaf(f1.x, w1, ax); ay = fmaf(f1.y, w1, ay); az = fmaf(f1.z, w1, az); aw = fmaf(f1.w, w1, aw);
        ax = fmaf(f2.x, w2, ax); ay = fmaf(f2.y, w2, ay); az = fmaf(f2.z, w2, az); aw = fmaf(f2.w, w2, aw);
        ax = fmaf(f3.x, w3, ax); ay = fmaf(f3.y, w3, ay); az = fmaf(f3.z, w3, az); aw = fmaf(f3.w, w3, aw);
    }
    for (; e < end; e++) {
        int s = g_csr[e];
        float w = g_dis[s] * disv;
        float4 f = ld4(T + (size_t)s * FF + c);
        ax = fmaf(f.x, w, ax); ay = fmaf(f.y, w, ay); az = fmaf(f.z, w, az); aw = fmaf(f.w, w, aw);
    }

    float4 b = ld4(bias + c);
    float4 o;
    o.x = elu1(ax + b.x);
    o.y = elu1(ay + b.y);
    o.z = elu1(az + b.z);
    o.w = elu1(aw + b.w);
    *(float4*)(Hout + (size_t)v * FF + c) = o;
}

// ---------------- final head: out[v] = dot(h[v], Wl) + bl ----------------
__global__ __launch_bounds__(256)
void head_kernel(const float* __restrict__ H, const float* __restrict__ Wl,
                 const float* __restrict__ bl, float* __restrict__ out) {
    int warp = threadIdx.x >> 5;
    int lane = threadIdx.x & 31;
    int v = blockIdx.x * 8 + warp;
    if (v >= NN) return;
    int c = lane * 4;
    float4 h = ld4(H + (size_t)v * FF + c);
    float4 w = ld4(Wl + c);
    float s = h.x * w.x + h.y * w.y + h.z * w.z + h.w * w.w;
#pragma unroll
    for (int off = 16; off > 0; off >>= 1) s += __shfl_down_sync(0xFFFFFFFFu, s, off);
    if (lane == 0) out[v] = s + bl[0];
}

// ---------------- launch ----------------
extern "C" void kernel_launch(void* const* d_in, const int* in_sizes, int n_in,
                              void* d_out, int out_size) {
    const float* x  = (const float*)d_in[0];   // [N,128]
    const float* Ws = (const float*)d_in[1];   // [3,128,128]
    const float* bs = (const float*)d_in[2];   // [3,128]
    const float* Wl = (const float*)d_in[3];   // [128,1]
    const float* bl = (const float*)d_in[4];   // [1]
    const int*   ei = (const int*)d_in[5];     // [2,E]
    const int* src = ei;
    const int* dst = ei + EE;
    float* out = (float*)d_out;

    float *bufA, *bufB;
    cudaGetSymbolAddress((void**)&bufA, g_bufA);
    cudaGetSymbolAddress((void**)&bufB, g_bufB);

    int nb = (NN + 255) / 256;  // 196

    // CSR build
    zero_cnt_kernel<<<nb, 256>>>();
    count_kernel<<<(EE + 255) / 256, 256>>>(dst);
    dis_kernel<<<nb, 256>>>();
    scan1_kernel<<<nb, 256>>>();
    scan2_kernel<<<1, 256>>>();
    scan3_kernel<<<nb, 256>>>();
    fill_kernel<<<(EE + 255) / 256, 256>>>(src, dst);

    int gemm_grid = (NN + BM - 1) / BM;   // 391
    int node_grid = (NN + 7) / 8;

    // layer 0: x -> bufA (t) -> bufB (h)
    gemm128_kernel<<<gemm_grid, 256>>>(x, Ws + 0 * FF * FF, bufA, NN);
    agg_elu_kernel<<<node_grid, 256>>>(bufA, bs + 0 * FF, bufB);
    // layer 1
    gemm128_kernel<<<gemm_grid, 256>>>(bufB, Ws + 1 * FF * FF, bufA, NN);
    agg_elu_kernel<<<node_grid, 256>>>(bufA, bs + 1 * FF, bufB);
    // layer 2
    gemm128_kernel<<<gemm_grid, 256>>>(bufB, Ws + 2 * FF * FF, bufA, NN);
    agg_elu_kernel<<<node_grid, 256>>>(bufA, bs + 2 * FF, bufB);
    // head
    head_kernel<<<node_grid, 256>>>(bufB, Wl, bl, out);
}

// round 3
// speedup vs baseline: 1.5010x; 1.1797x over previous
#include <cuda_runtime.h>
#include <cuda_fp16.h>
#include <cuda_bf16.h>
#include <math.h>

#define NN 50000
#define EE 800000
#define FF 128

typedef unsigned long long u64;

// ---------------- scratch (static device globals; no allocation) ----------------
__device__ int    g_cnt[NN];
__device__ float  g_dis[NN];
__device__ int    g_rowstart[NN + 1];
__device__ int    g_fillptr[NN];
__device__ int    g_csr[EE];
__device__ int    g_blocksum[256];
__device__ int    g_blockoff[256];
__device__ __half g_bufT[(size_t)NN * FF];   // transformed features (fp16)
__device__ float  g_bufH[(size_t)NN * FF];   // post-ELU features (fp32)

// ---------------- small helpers ----------------
__device__ __forceinline__ float4 ld4(const float* p) { return *(const float4*)p; }

__device__ __forceinline__ u64 ffma2(u64 a, u64 b, u64 c) {
    u64 d;
    asm("fma.rn.f32x2 %0, %1, %2, %3;" : "=l"(d) : "l"(a), "l"(b), "l"(c));
    return d;
}
__device__ __forceinline__ u64 pack2(float lo, float hi) {
    u64 d;
    asm("mov.b64 %0, {%1, %2};" : "=l"(d) : "f"(lo), "f"(hi));
    return d;
}
__device__ __forceinline__ void unpack2(u64 v, float& lo, float& hi) {
    asm("mov.b64 {%0, %1}, %2;" : "=f"(lo), "=f"(hi) : "l"(v));
}

// ---------------- CSR build ----------------
__global__ void zero_cnt_kernel() {
    int i = blockIdx.x * blockDim.x + threadIdx.x;
    if (i < NN) g_cnt[i] = 0;
}

__global__ void count_kernel(const int* __restrict__ dst) {
    int i = blockIdx.x * blockDim.x + threadIdx.x;
    if (i < EE) atomicAdd(&g_cnt[dst[i]], 1);
}

__global__ void dis_kernel() {
    int i = blockIdx.x * blockDim.x + threadIdx.x;
    if (i < NN) g_dis[i] = rsqrtf((float)g_cnt[i] + 1.0f);  // +1 self loop
}

__device__ __forceinline__ int block_exclusive_scan_256(int val, int tid, int* total_out) {
    int lane = tid & 31, w = tid >> 5;
    int x = val;
#pragma unroll
    for (int off = 1; off < 32; off <<= 1) {
        int y = __shfl_up_sync(0xFFFFFFFFu, x, off);
        if (lane >= off) x += y;
    }
    __shared__ int ws[8];
    if (lane == 31) ws[w] = x;
    __syncthreads();
    __shared__ int wo[9];
    if (tid == 0) {
        int run = 0;
#pragma unroll
        for (int i = 0; i < 8; i++) { wo[i] = run; run += ws[i]; }
        wo[8] = run;
    }
    __syncthreads();
    *total_out = wo[8];
    return x - val + wo[w];
}

__global__ void scan1_kernel() {  // grid=196, block=256
    int b = blockIdx.x, t = threadIdx.x;
    int i = b * 256 + t;
    int val = (i < NN) ? g_cnt[i] : 0;
    int total;
    int excl = block_exclusive_scan_256(val, t, &total);
    if (i < NN) g_rowstart[i] = excl;
    if (t == 0) g_blocksum[b] = total;
}

__global__ void scan2_kernel() {  // 1 block, 256 threads
    int t = threadIdx.x;
    int nb = (NN + 255) / 256;
    int val = (t < nb) ? g_blocksum[t] : 0;
    int total;
    int excl = block_exclusive_scan_256(val, t, &total);
    g_blockoff[t] = excl;
}

__global__ void scan3_kernel() {  // grid=196, block=256
    int b = blockIdx.x, t = threadIdx.x;
    int i = b * 256 + t;
    if (i < NN) {
        int rs = g_rowstart[i] + g_blockoff[b];
        g_rowstart[i] = rs;
        g_fillptr[i]  = rs;
    }
    if (i == 0) g_rowstart[NN] = EE;
}

__global__ void fill_kernel(const int* __restrict__ src, const int* __restrict__ dst) {
    int i = blockIdx.x * blockDim.x + threadIdx.x;
    if (i < EE) {
        int d = dst[i];
        int p = atomicAdd(&g_fillptr[d], 1);
        g_csr[p] = src[i];
    }
}

// ---------------- GEMM: C_half[M x 128] = A[M x 128] * B[128 x 128] ----------------
#define BM 128
#define BN 128
#define BK 32
__global__ __launch_bounds__(256, 2)
void gemm128_kernel(const float* __restrict__ A, const float* __restrict__ B,
                    __half* __restrict__ C, int M) {
    __shared__ float As[BK][BM];  // [k][m] — m contiguous: rows pair naturally for f32x2
    __shared__ float Bs[BK][BN];  // [k][n]
    int tid = threadIdx.x;        // 256 threads
    int m0 = blockIdx.x * BM;

    u64 accp[4][8];  // 4 row-pairs x 8 cols, packed f32x2
#pragma unroll
    for (int i = 0; i < 4; i++)
#pragma unroll
        for (int j = 0; j < 8; j++) accp[i][j] = 0ull;

    int arow  = tid >> 3;
    int acol4 = (tid & 7) * 4;
    int brow  = tid >> 5;
    int bcol4 = (tid & 31) * 4;
    int ty = tid >> 4, tx = tid & 15;

    for (int k0 = 0; k0 < FF; k0 += BK) {
#pragma unroll
        for (int i = 0; i < 4; i++) {
            int r = arow + 32 * i;
            int gm = m0 + r;
            float4 v = (gm < M) ? ld4(A + (size_t)gm * FF + k0 + acol4)
                                : make_float4(0.f, 0.f, 0.f, 0.f);
            As[acol4 + 0][r] = v.x;
            As[acol4 + 1][r] = v.y;
            As[acol4 + 2][r] = v.z;
            As[acol4 + 3][r] = v.w;
        }
#pragma unroll
        for (int i = 0; i < 4; i++) {
            int kk = brow + 8 * i;
            *(float4*)&Bs[kk][bcol4] = ld4(B + (size_t)(k0 + kk) * FF + bcol4);
        }
        __syncthreads();

#pragma unroll
        for (int k = 0; k < BK; k++) {
            const u64* arowp = (const u64*)&As[k][ty * 8];
            u64 ap0 = arowp[0], ap1 = arowp[1], ap2 = arowp[2], ap3 = arowp[3];
            float b[8];
            *(float4*)(b)     = *(float4*)&Bs[k][tx * 8];
            *(float4*)(b + 4) = *(float4*)&Bs[k][tx * 8 + 4];
            u64 bd[8];
#pragma unroll
            for (int j = 0; j < 8; j++) bd[j] = pack2(b[j], b[j]);
#pragma unroll
            for (int j = 0; j < 8; j++) {
                accp[0][j] = ffma2(ap0, bd[j], accp[0][j]);
                accp[1][j] = ffma2(ap1, bd[j], accp[1][j]);
                accp[2][j] = ffma2(ap2, bd[j], accp[2][j]);
                accp[3][j] = ffma2(ap3, bd[j], accp[3][j]);
            }
        }
        __syncthreads();
    }

#pragma unroll
    for (int ii = 0; ii < 4; ii++) {
        float lo[8], hi[8];
#pragma unroll
        for (int j = 0; j < 8; j++) unpack2(accp[ii][j], lo[j], hi[j]);
        int gm = m0 + ty * 8 + 2 * ii;
        if (gm < M) {
            __half2 h0 = __floats2half2_rn(lo[0], lo[1]);
            __half2 h1 = __floats2half2_rn(lo[2], lo[3]);
            __half2 h2 = __floats2half2_rn(lo[4], lo[5]);
            __half2 h3 = __floats2half2_rn(lo[6], lo[7]);
            __half2* cp = (__half2*)(C + (size_t)gm * FF + tx * 8);
            uint4 packed = make_uint4(*(unsigned*)&h0, *(unsigned*)&h1,
                                      *(unsigned*)&h2, *(unsigned*)&h3);
            *(uint4*)cp = packed;
        }
        if (gm + 1 < M) {
            __half2 h0 = __floats2half2_rn(hi[0], hi[1]);
            __half2 h1 = __floats2half2_rn(hi[2], hi[3]);
            __half2 h2 = __floats2half2_rn(hi[4], hi[5]);
            __half2 h3 = __floats2half2_rn(hi[6], hi[7]);
            __half2* cp = (__half2*)(C + (size_t)(gm + 1) * FF + tx * 8);
            uint4 packed = make_uint4(*(unsigned*)&h0, *(unsigned*)&h1,
                                      *(unsigned*)&h2, *(unsigned*)&h3);
            *(uint4*)cp = packed;
        }
    }
}

// ---------------- aggregation + bias + ELU (warp per node, fp16 gather) ----------------
__device__ __forceinline__ float elu1(float v) { return v > 0.f ? v : expm1f(v); }

__device__ __forceinline__ void gather_row(const __half* __restrict__ T, int row, int lane,
                                           float& fx, float& fy, float& fz, float& fw) {
    uint2 raw = *((const uint2*)(T + (size_t)row * FF) + lane);
    __half2 a = *(__half2*)&raw.x;
    __half2 b = *(__half2*)&raw.y;
    float2 f0 = __half22float2(a);
    float2 f1 = __half22float2(b);
    fx = f0.x; fy = f0.y; fz = f1.x; fw = f1.y;
}

__global__ __launch_bounds__(256)
void agg_elu_kernel(const __half* __restrict__ T, const float* __restrict__ bias,
                    float* __restrict__ Hout) {
    int warp = threadIdx.x >> 5;
    int lane = threadIdx.x & 31;
    int v = blockIdx.x * 8 + warp;
    if (v >= NN) return;
    int c = lane * 4;

    float disv = g_dis[v];
    float wself = disv * disv;
    float tx, tyv, tz, tw;
    gather_row(T, v, lane, tx, tyv, tz, tw);
    float ax = tx * wself, ay = tyv * wself, az = tz * wself, aw = tw * wself;

    int beg = g_rowstart[v];
    int end = g_rowstart[v + 1];
    int e = beg;
    for (; e + 4 <= end; e += 4) {
        int s0 = g_csr[e + 0], s1 = g_csr[e + 1], s2 = g_csr[e + 2], s3 = g_csr[e + 3];
        float w0 = g_dis[s0] * disv, w1 = g_dis[s1] * disv;
        float w2 = g_dis[s2] * disv, w3 = g_dis[s3] * disv;
        float x0, y0, z0, q0, x1, y1, z1, q1, x2, y2, z2, q2, x3, y3, z3, q3;
        gather_row(T, s0, lane, x0, y0, z0, q0);
        gather_row(T, s1, lane, x1, y1, z1, q1);
        gather_row(T, s2, lane, x2, y2, z2, q2);
        gather_row(T, s3, lane, x3, y3, z3, q3);
        ax = fmaf(x0, w0, ax); ay = fmaf(y0, w0, ay); az = fmaf(z0, w0, az); aw = fmaf(q0, w0, aw);
        ax = fmaf(x1, w1, ax); ay = fmaf(y1, w1, ay); az = fmaf(z1, w1, az); aw = fmaf(q1, w1, aw);
        ax = fmaf(x2, w2, ax); ay = fmaf(y2, w2, ay); az = fmaf(z2, w2, az); aw = fmaf(q2, w2, aw);
        ax = fmaf(x3, w3, ax); ay = fmaf(y3, w3, ay); az = fmaf(z3, w3, az); aw = fmaf(q3, w3, aw);
    }
    for (; e < end; e++) {
        int s = g_csr[e];
        float w = g_dis[s] * disv;
        float fx, fy, fz, fw;
        gather_row(T, s, lane, fx, fy, fz, fw);
        ax = fmaf(fx, w, ax); ay = fmaf(fy, w, ay); az = fmaf(fz, w, az); aw = fmaf(fw, w, aw);
    }

    float4 b = ld4(bias + c);
    float4 o;
    o.x = elu1(ax + b.x);
    o.y = elu1(ay + b.y);
    o.z = elu1(az + b.z);
    o.w = elu1(aw + b.w);
    *(float4*)(Hout + (size_t)v * FF + c) = o;
}

// layer-2 agg fused with the linear head: out[v] = dot(ELU(agg+b), Wl) + bl
__global__ __launch_bounds__(256)
void agg_elu_head_kernel(const __half* __restrict__ T, const float* __restrict__ bias,
                         const float* __restrict__ Wl, const float* __restrict__ bl,
                         float* __restrict__ out) {
    int warp = threadIdx.x >> 5;
    int lane = threadIdx.x & 31;
    int v = blockIdx.x * 8 + warp;
    if (v >= NN) return;
    int c = lane * 4;

    float disv = g_dis[v];
    float wself = disv * disv;
    float tx, tyv, tz, tw;
    gather_row(T, v, lane, tx, tyv, tz, tw);
    float ax = tx * wself, ay = tyv * wself, az = tz * wself, aw = tw * wself;

    int beg = g_rowstart[v];
    int end = g_rowstart[v + 1];
    int e = beg;
    for (; e + 4 <= end; e += 4) {
        int s0 = g_csr[e + 0], s1 = g_csr[e + 1], s2 = g_csr[e + 2], s3 = g_csr[e + 3];
        float w0 = g_dis[s0] * disv, w1 = g_dis[s1] * disv;
        float w2 = g_dis[s2] * disv, w3 = g_dis[s3] * disv;
        float x0, y0, z0, q0, x1, y1, z1, q1, x2, y2, z2, q2, x3, y3, z3, q3;
        gather_row(T, s0, lane, x0, y0, z0, q0);
        gather_row(T, s1, lane, x1, y1, z1, q1);
        gather_row(T, s2, lane, x2, y2, z2, q2);
        gather_row(T, s3, lane, x3, y3, z3, q3);
        ax = fmaf(x0, w0, ax); ay = fmaf(y0, w0, ay); az = fmaf(z0, w0, az); aw = fmaf(q0, w0, aw);
        ax = fmaf(x1, w1, ax); ay = fmaf(y1, w1, ay); az = fmaf(z1, w1, az); aw = fmaf(q1, w1, aw);
        ax = fmaf(x2, w2, ax); ay = fmaf(y2, w2, ay); az = fmaf(z2, w2, az); aw = fmaf(q2, w2, aw);
        ax = fmaf(x3, w3, ax); ay = fmaf(y3, w3, ay); az = fmaf(z3, w3, az); aw = fmaf(q3, w3, aw);
    }
    for (; e < end; e++) {
        int s = g_csr[e];
        float w = g_dis[s] * disv;
        float fx, fy, fz, fw;
        gather_row(T, s, lane, fx, fy, fz, fw);
        ax = fmaf(fx, w, ax); ay = fmaf(fy, w, ay); az = fmaf(fz, w, az); aw = fmaf(fw, w, aw);
    }

    float4 b = ld4(bias + c);
    float4 wl = ld4(Wl + c);
    float s = elu1(ax + b.x) * wl.x + elu1(ay + b.y) * wl.y
            + elu1(az + b.z) * wl.z + elu1(aw + b.w) * wl.w;
#pragma unroll
    for (int off = 16; off > 0; off >>= 1) s += __shfl_down_sync(0xFFFFFFFFu, s, off);
    if (lane == 0) out[v] = s + bl[0];
}

// ---------------- launch ----------------
extern "C" void kernel_launch(void* const* d_in, const int* in_sizes, int n_in,
                              void* d_out, int out_size) {
    const float* x  = (const float*)d_in[0];   // [N,128]
    const float* Ws = (const float*)d_in[1];   // [3,128,128]
    const float* bs = (const float*)d_in[2];   // [3,128]
    const float* Wl = (const float*)d_in[3];   // [128,1]
    const float* bl = (const float*)d_in[4];   // [1]
    const int*   ei = (const int*)d_in[5];     // [2,E]
    const int* src = ei;
    const int* dst = ei + EE;
    float* out = (float*)d_out;

    __half* bufT;
    float*  bufH;
    cudaGetSymbolAddress((void**)&bufT, g_bufT);
    cudaGetSymbolAddress((void**)&bufH, g_bufH);

    // lazy one-time side stream + events for CSR/GEMM0 overlap
    static cudaStream_t s_side = (cudaStream_t)0;
    static cudaEvent_t  s_fork = nullptr, s_join = nullptr;
    static int s_init = 0;
    if (!s_init) {
        cudaStream_t tmp;
        if (cudaStreamCreateWithFlags(&tmp, cudaStreamNonBlocking) == cudaSuccess) {
            cudaEvent_t e1, e2;
            if (cudaEventCreateWithFlags(&e1, cudaEventDisableTiming) == cudaSuccess &&
                cudaEventCreateWithFlags(&e2, cudaEventDisableTiming) == cudaSuccess) {
                s_side = tmp; s_fork = e1; s_join = e2;
            }
        }
        s_init = 1;
    }

    int nb = (NN + 255) / 256;            // 196
    int gemm_grid = (NN + BM - 1) / BM;   // 391
    int node_grid = (NN + 7) / 8;

    if (s_side) {
        // fork: CSR build runs concurrently with GEMM0
        cudaEventRecord(s_fork, 0);
        cudaStreamWaitEvent(s_side, s_fork, 0);
        zero_cnt_kernel<<<nb, 256, 0, s_side>>>();
        count_kernel<<<(EE + 255) / 256, 256, 0, s_side>>>(dst);
        dis_kernel<<<nb, 256, 0, s_side>>>();
        scan1_kernel<<<nb, 256, 0, s_side>>>();
        scan2_kernel<<<1, 256, 0, s_side>>>();
        scan3_kernel<<<nb, 256, 0, s_side>>>();
        fill_kernel<<<(EE + 255) / 256, 256, 0, s_side>>>(src, dst);
        cudaEventRecord(s_join, s_side);

        gemm128_kernel<<<gemm_grid, 256>>>(x, Ws + 0 * FF * FF, bufT, NN);
        cudaStreamWaitEvent(0, s_join, 0);  // join before first agg
    } else {
        zero_cnt_kernel<<<nb, 256>>>();
        count_kernel<<<(EE + 255) / 256, 256>>>(dst);
        dis_kernel<<<nb, 256>>>();
        scan1_kernel<<<nb, 256>>>();
        scan2_kernel<<<1, 256>>>();
        scan3_kernel<<<nb, 256>>>();
        fill_kernel<<<(EE + 255) / 256, 256>>>(src, dst);
        gemm128_kernel<<<gemm_grid, 256>>>(x, Ws + 0 * FF * FF, bufT, NN);
    }

    // layer 0
    agg_elu_kernel<<<node_grid, 256>>>(bufT, bs + 0 * FF, bufH);
    // layer 1
    gemm128_kernel<<<gemm_grid, 256>>>(bufH, Ws + 1 * FF * FF, bufT, NN);
    agg_elu_kernel<<<node_grid, 256>>>(bufT, bs + 1 * FF, bufH);
    // layer 2 + fused head
    gemm128_kernel<<<gemm_grid, 256>>>(bufH, Ws + 2 * FF * FF, bufT, NN);
    agg_elu_head_kernel<<<node_grid, 256>>>(bufT, bs + 2 * FF, Wl, bl, out);
}

// round 5
// speedup vs baseline: 2.4225x; 1.6139x over previous
#include <cuda_runtime.h>
#include <cuda_fp16.h>
#include <cuda_bf16.h>
#include <math.h>

#define NN 50000
#define EE 800000
#define FF 128

typedef unsigned long long u64;

// ---------------- scratch (static device globals; no allocation) ----------------
__device__ int    g_cnt[NN];
__device__ float  g_dis[NN];
__device__ int    g_rowstart[NN + 1];
__device__ int    g_fillptr[NN];
__device__ int    g_csr[EE];
__device__ int    g_blocksum[256];
__device__ int    g_blockoff[256];
__device__ __half g_bufT[(size_t)NN * FF];   // transformed features (fp16)
__device__ float  g_bufH[(size_t)NN * FF];   // post-ELU features (fp32)

// ---------------- small helpers ----------------
__device__ __forceinline__ float4 ld4(const float* p) { return *(const float4*)p; }

__device__ __forceinline__ unsigned smem_u32(const void* p) {
    unsigned a;
    asm("{ .reg .u64 t; cvta.to.shared.u64 t, %1; cvt.u32.u64 %0, t; }" : "=r"(a) : "l"(p));
    return a;
}
__device__ __forceinline__ void ldsm_x4(unsigned addr, unsigned& r0, unsigned& r1,
                                        unsigned& r2, unsigned& r3) {
    asm volatile("ldmatrix.sync.aligned.m8n8.x4.shared.b16 {%0,%1,%2,%3}, [%4];"
                 : "=r"(r0), "=r"(r1), "=r"(r2), "=r"(r3) : "r"(addr));
}
__device__ __forceinline__ void ldsm_x4t(unsigned addr, unsigned& r0, unsigned& r1,
                                         unsigned& r2, unsigned& r3) {
    asm volatile("ldmatrix.sync.aligned.m8n8.x4.trans.shared.b16 {%0,%1,%2,%3}, [%4];"
                 : "=r"(r0), "=r"(r1), "=r"(r2), "=r"(r3) : "r"(addr));
}
__device__ __forceinline__ void mma16816(float* d, const unsigned* a, const unsigned* b) {
    asm volatile(
        "mma.sync.aligned.m16n8k16.row.col.f32.f16.f16.f32 "
        "{%0,%1,%2,%3},{%4,%5,%6,%7},{%8,%9},{%0,%1,%2,%3};"
        : "+f"(d[0]), "+f"(d[1]), "+f"(d[2]), "+f"(d[3])
        : "r"(a[0]), "r"(a[1]), "r"(a[2]), "r"(a[3]), "r"(b[0]), "r"(b[1]));
}

// ---------------- CSR build ----------------
__global__ void zero_cnt_kernel() {
    int i = blockIdx.x * blockDim.x + threadIdx.x;
    if (i < NN) g_cnt[i] = 0;
}

__global__ void count_kernel(const int* __restrict__ dst) {
    int i = blockIdx.x * blockDim.x + threadIdx.x;
    if (i < EE) atomicAdd(&g_cnt[dst[i]], 1);
}

__global__ void dis_kernel() {
    int i = blockIdx.x * blockDim.x + threadIdx.x;
    if (i < NN) g_dis[i] = rsqrtf((float)g_cnt[i] + 1.0f);  // +1 self loop
}

__device__ __forceinline__ int block_exclusive_scan_256(int val, int tid, int* total_out) {
    int lane = tid & 31, w = tid >> 5;
    int x = val;
#pragma unroll
    for (int off = 1; off < 32; off <<= 1) {
        int y = __shfl_up_sync(0xFFFFFFFFu, x, off);
        if (lane >= off) x += y;
    }
    __shared__ int ws[8];
    if (lane == 31) ws[w] = x;
    __syncthreads();
    __shared__ int wo[9];
    if (tid == 0) {
        int run = 0;
#pragma unroll
        for (int i = 0; i < 8; i++) { wo[i] = run; run += ws[i]; }
        wo[8] = run;
    }
    __syncthreads();
    *total_out = wo[8];
    return x - val + wo[w];
}

__global__ void scan1_kernel() {
    int b = blockIdx.x, t = threadIdx.x;
    int i = b * 256 + t;
    int val = (i < NN) ? g_cnt[i] : 0;
    int total;
    int excl = block_exclusive_scan_256(val, t, &total);
    if (i < NN) g_rowstart[i] = excl;
    if (t == 0) g_blocksum[b] = total;
}

__global__ void scan2_kernel() {
    int t = threadIdx.x;
    int nb = (NN + 255) / 256;
    int val = (t < nb) ? g_blocksum[t] : 0;
    int total;
    int excl = block_exclusive_scan_256(val, t, &total);
    g_blockoff[t] = excl;
}

__global__ void scan3_kernel() {
    int b = blockIdx.x, t = threadIdx.x;
    int i = b * 256 + t;
    if (i < NN) {
        int rs = g_rowstart[i] + g_blockoff[b];
        g_rowstart[i] = rs;
        g_fillptr[i]  = rs;
    }
    if (i == 0) g_rowstart[NN] = EE;
}

__global__ void fill_kernel(const int* __restrict__ src, const int* __restrict__ dst) {
    int i = blockIdx.x * blockDim.x + threadIdx.x;
    if (i < EE) {
        int d = dst[i];
        int p = atomicAdd(&g_fillptr[d], 1);
        g_csr[p] = src[i];
    }
}

// ---------------- tensor-core GEMM: C_half[M x 128] = A[M x 128] * W[128 x 128] ----------------
#define AST 136   // smem half-stride (128 + 8 pad)
#define GEMM_SMEM (2 * 128 * AST * 2)   // As + Bs, bytes

extern __shared__ __align__(16) __half smx[];

__global__ __launch_bounds__(256)
void gemm_tc_kernel(const float* __restrict__ A, const float* __restrict__ W,
                    __half* __restrict__ C, int M) {
    __half* As = smx;               // [128][AST]
    __half* Bs = smx + 128 * AST;   // [128][AST], row = k, col = n
    int tid = threadIdx.x;
    int m0 = blockIdx.x * 128;

    // load + convert A tile (fp32 -> fp16)
#pragma unroll
    for (int p = 0; p < 16; p++) {
        int idx = p * 256 + tid;          // 0..4095
        int row = idx >> 5, c4 = (idx & 31) * 4;
        int gm = m0 + row;
        float4 v = (gm < M) ? ld4(A + (size_t)gm * FF + c4) : make_float4(0.f, 0.f, 0.f, 0.f);
        __half2 h0 = __floats2half2_rn(v.x, v.y);
        __half2 h1 = __floats2half2_rn(v.z, v.w);
        *(uint2*)&As[row * AST + c4] = make_uint2(*(unsigned*)&h0, *(unsigned*)&h1);
    }
    // load + convert W tile
#pragma unroll
    for (int p = 0; p < 16; p++) {
        int idx = p * 256 + tid;
        int row = idx >> 5, c4 = (idx & 31) * 4;
        float4 v = ld4(W + (size_t)row * FF + c4);
        __half2 h0 = __floats2half2_rn(v.x, v.y);
        __half2 h1 = __floats2half2_rn(v.z, v.w);
        *(uint2*)&Bs[row * AST + c4] = make_uint2(*(unsigned*)&h0, *(unsigned*)&h1);
    }
    __syncthreads();

    int warp = tid >> 5, lane = tid & 31;
    int wm = (warp & 3) * 32;     // warp M offset (32 rows)
    int wn = (warp >> 2) * 64;    // warp N offset (64 cols)

    float d[2][8][4];
#pragma unroll
    for (int i = 0; i < 2; i++)
#pragma unroll
        for (int j = 0; j < 8; j++)
#pragma unroll
            for (int q = 0; q < 4; q++) d[i][j][q] = 0.f;

    int lrow = lane & 15;
    int lcol8 = (lane >> 4) << 3;
    unsigned aoff0 = smem_u32(&As[(wm + lrow) * AST]);
    unsigned aoff1 = smem_u32(&As[(wm + 16 + lrow) * AST]);
    unsigned boff  = smem_u32(&Bs[lrow * AST]);

#pragma unroll
    for (int k0 = 0; k0 < FF; k0 += 16) {
        unsigned a0[4], a1[4];
        ldsm_x4(aoff0 + (k0 + lcol8) * 2, a0[0], a0[1], a0[2], a0[3]);
        ldsm_x4(aoff1 + (k0 + lcol8) * 2, a1[0], a1[1], a1[2], a1[3]);
        unsigned b[4][4];
#pragma unroll
        for (int nj = 0; nj < 4; nj++)
            ldsm_x4t(boff + (k0 * AST + wn + nj * 16 + lcol8) * 2,
                     b[nj][0], b[nj][1], b[nj][2], b[nj][3]);
#pragma unroll
        for (int nj = 0; nj < 4; nj++) {
            mma16816(d[0][2 * nj],     a0, &b[nj][0]);
            mma16816(d[0][2 * nj + 1], a0, &b[nj][2]);
            mma16816(d[1][2 * nj],     a1, &b[nj][0]);
            mma16816(d[1][2 * nj + 1], a1, &b[nj][2]);
        }
    }

    // stage C (fp16) through smem (reuse As), then coalesced store
    __syncthreads();
    __half* Cs = As;
    int crow = lane >> 2;
    int ccol = (lane & 3) * 2;
#pragma unroll
    for (int mi = 0; mi < 2; mi++) {
#pragma unroll
        for (int jj = 0; jj < 8; jj++) {
            int r = wm + mi * 16 + crow;
            int c = wn + jj * 8 + ccol;
            __half2 lo = __floats2half2_rn(d[mi][jj][0], d[mi][jj][1]);
            __half2 hi = __floats2half2_rn(d[mi][jj][2], d[mi][jj][3]);
            *(__half2*)&Cs[r * AST + c]       = lo;
            *(__half2*)&Cs[(r + 8) * AST + c] = hi;
        }
    }
    __syncthreads();
#pragma unroll
    for (int p = 0; p < 8; p++) {
        int idx = p * 256 + tid;          // 0..2047
        int row = idx >> 4, c8 = (idx & 15) * 8;
        int gm = m0 + row;
        if (gm < M)
            *(uint4*)(C + (size_t)gm * FF + c8) = *(uint4*)&Cs[row * AST + c8];
    }
}

// ---------------- aggregation + bias + ELU (warp per node, fp16 gather) ----------------
__device__ __forceinline__ float elu1(float v) { return v > 0.f ? v : expm1f(v); }

__device__ __forceinline__ void gather_row(const __half* __restrict__ T, int row, int lane,
                                           float& fx, float& fy, float& fz, float& fw) {
    uint2 raw = *((const uint2*)(T + (size_t)row * FF) + lane);
    __half2 a = *(__half2*)&raw.x;
    __half2 b = *(__half2*)&raw.y;
    float2 f0 = __half22float2(a);
    float2 f1 = __half22float2(b);
    fx = f0.x; fy = f0.y; fz = f1.x; fw = f1.y;
}

__global__ __launch_bounds__(256)
void agg_elu_kernel(const __half* __restrict__ T, const float* __restrict__ bias,
                    float* __restrict__ Hout) {
    int warp = threadIdx.x >> 5;
    int lane = threadIdx.x & 31;
    int v = blockIdx.x * 8 + warp;
    if (v >= NN) return;
    int c = lane * 4;

    float disv = g_dis[v];
    float wself = disv * disv;
    float tx, tyv, tz, tw;
    gather_row(T, v, lane, tx, tyv, tz, tw);
    float ax = tx * wself, ay = tyv * wself, az = tz * wself, aw = tw * wself;

    int beg = g_rowstart[v];
    int end = g_rowstart[v + 1];
    int e = beg;
    for (; e + 4 <= end; e += 4) {
        int s0 = g_csr[e + 0], s1 = g_csr[e + 1], s2 = g_csr[e + 2], s3 = g_csr[e + 3];
        float w0 = g_dis[s0] * disv, w1 = g_dis[s1] * disv;
        float w2 = g_dis[s2] * disv, w3 = g_dis[s3] * disv;
        float x0, y0, z0, q0, x1, y1, z1, q1, x2, y2, z2, q2, x3, y3, z3, q3;
        gather_row(T, s0, lane, x0, y0, z0, q0);
        gather_row(T, s1, lane, x1, y1, z1, q1);
        gather_row(T, s2, lane, x2, y2, z2, q2);
        gather_row(T, s3, lane, x3, y3, z3, q3);
        ax = fmaf(x0, w0, ax); ay = fmaf(y0, w0, ay); az = fmaf(z0, w0, az); aw = fmaf(q0, w0, aw);
        ax = fmaf(x1, w1, ax); ay = fmaf(y1, w1, ay); az = fmaf(z1, w1, az); aw = fmaf(q1, w1, aw);
        ax = fmaf(x2, w2, ax); ay = fmaf(y2, w2, ay); az = fmaf(z2, w2, az); aw = fmaf(q2, w2, aw);
        ax = fmaf(x3, w3, ax); ay = fmaf(y3, w3, ay); az = fmaf(z3, w3, az); aw = fmaf(q3, w3, aw);
    }
    for (; e < end; e++) {
        int s = g_csr[e];
        float w = g_dis[s] * disv;
        float fx, fy, fz, fw;
        gather_row(T, s, lane, fx, fy, fz, fw);
        ax = fmaf(fx, w, ax); ay = fmaf(fy, w, ay); az = fmaf(fz, w, az); aw = fmaf(fw, w, aw);
    }

    float4 b = ld4(bias + c);
    float4 o;
    o.x = elu1(ax + b.x);
    o.y = elu1(ay + b.y);
    o.z = elu1(az + b.z);
    o.w = elu1(aw + b.w);
    *(float4*)(Hout + (size_t)v * FF + c) = o;
}

// layer-2 agg fused with the linear head
__global__ __launch_bounds__(256)
void agg_elu_head_kernel(const __half* __restrict__ T, const float* __restrict__ bias,
                         const float* __restrict__ Wl, const float* __restrict__ bl,
                         float* __restrict__ out) {
    int warp = threadIdx.x >> 5;
    int lane = threadIdx.x & 31;
    int v = blockIdx.x * 8 + warp;
    if (v >= NN) return;
    int c = lane * 4;

    float disv = g_dis[v];
    float wself = disv * disv;
    float tx, tyv, tz, tw;
    gather_row(T, v, lane, tx, tyv, tz, tw);
    float ax = tx * wself, ay = tyv * wself, az = tz * wself, aw = tw * wself;

    int beg = g_rowstart[v];
    int end = g_rowstart[v + 1];
    int e = beg;
    for (; e + 4 <= end; e += 4) {
        int s0 = g_csr[e + 0], s1 = g_csr[e + 1], s2 = g_csr[e + 2], s3 = g_csr[e + 3];
        float w0 = g_dis[s0] * disv, w1 = g_dis[s1] * disv;
        float w2 = g_dis[s2] * disv, w3 = g_dis[s3] * disv;
        float x0, y0, z0, q0, x1, y1, z1, q1, x2, y2, z2, q2, x3, y3, z3, q3;
        gather_row(T, s0, lane, x0, y0, z0, q0);
        gather_row(T, s1, lane, x1, y1, z1, q1);
        gather_row(T, s2, lane, x2, y2, z2, q2);
        gather_row(T, s3, lane, x3, y3, z3, q3);
        ax = fmaf(x0, w0, ax); ay = fmaf(y0, w0, ay); az = fmaf(z0, w0, az); aw = fmaf(q0, w0, aw);
        ax = fmaf(x1, w1, ax); ay = fmaf(y1, w1, ay); az = fmaf(z1, w1, az); aw = fmaf(q1, w1, aw);
        ax = fmaf(x2, w2, ax); ay = fmaf(y2, w2, ay); az = fmaf(z2, w2, az); aw = fmaf(q2, w2, aw);
        ax = fmaf(x3, w3, ax); ay = fmaf(y3, w3, ay); az = fmaf(z3, w3, az); aw = fmaf(q3, w3, aw);
    }
    for (; e < end; e++) {
        int s = g_csr[e];
        float w = g_dis[s] * disv;
        float fx, fy, fz, fw;
        gather_row(T, s, lane, fx, fy, fz, fw);
        ax = fmaf(fx, w, ax); ay = fmaf(fy, w, ay); az = fmaf(fz, w, az); aw = fmaf(fw, w, aw);
    }

    float4 b = ld4(bias + c);
    float4 wl = ld4(Wl + c);
    float s = elu1(ax + b.x) * wl.x + elu1(ay + b.y) * wl.y
            + elu1(az + b.z) * wl.z + elu1(aw + b.w) * wl.w;
#pragma unroll
    for (int off = 16; off > 0; off >>= 1) s += __shfl_down_sync(0xFFFFFFFFu, s, off);
    if (lane == 0) out[v] = s + bl[0];
}

// ---------------- launch ----------------
extern "C" void kernel_launch(void* const* d_in, const int* in_sizes, int n_in,
                              void* d_out, int out_size) {
    const float* x  = (const float*)d_in[0];   // [N,128]
    const float* Ws = (const float*)d_in[1];   // [3,128,128]
    const float* bs = (const float*)d_in[2];   // [3,128]
    const float* Wl = (const float*)d_in[3];   // [128,1]
    const float* bl = (const float*)d_in[4];   // [1]
    const int*   ei = (const int*)d_in[5];     // [2,E]
    const int* src = ei;
    const int* dst = ei + EE;
    float* out = (float*)d_out;

    __half* bufT;
    float*  bufH;
    cudaGetSymbolAddress((void**)&bufT, g_bufT);
    cudaGetSymbolAddress((void**)&bufH, g_bufH);

    static cudaStream_t s_side = (cudaStream_t)0;
    static cudaEvent_t  s_fork = nullptr, s_join = nullptr;
    static int s_init = 0;
    if (!s_init) {
        cudaFuncSetAttribute(gemm_tc_kernel,
                             cudaFuncAttributeMaxDynamicSharedMemorySize, GEMM_SMEM);
        cudaStream_t tmp;
        if (cudaStreamCreateWithFlags(&tmp, cudaStreamNonBlocking) == cudaSuccess) {
            cudaEvent_t e1, e2;
            if (cudaEventCreateWithFlags(&e1, cudaEventDisableTiming) == cudaSuccess &&
                cudaEventCreateWithFlags(&e2, cudaEventDisableTiming) == cudaSuccess) {
                s_side = tmp; s_fork = e1; s_join = e2;
            }
        }
        s_init = 1;
    }

    int nb = (NN + 255) / 256;            // 196
    int gemm_grid = (NN + 127) / 128;     // 391
    int node_grid = (NN + 7) / 8;

    if (s_side) {
        cudaEventRecord(s_fork, 0);
        cudaStreamWaitEvent(s_side, s_fork, 0);
        zero_cnt_kernel<<<nb, 256, 0, s_side>>>();
        count_kernel<<<(EE + 255) / 256, 256, 0, s_side>>>(dst);
        dis_kernel<<<nb, 256, 0, s_side>>>();
        scan1_kernel<<<nb, 256, 0, s_side>>>();
        scan2_kernel<<<1, 256, 0, s_side>>>();
        scan3_kernel<<<nb, 256, 0, s_side>>>();
        fill_kernel<<<(EE + 255) / 256, 256, 0, s_side>>>(src, dst);
        cudaEventRecord(s_join, s_side);

        gemm_tc_kernel<<<gemm_grid, 256, GEMM_SMEM>>>(x, Ws + 0 * FF * FF, bufT, NN);
        cudaStreamWaitEvent(0, s_join, 0);
    } else {
        zero_cnt_kernel<<<nb, 256>>>();
        count_kernel<<<(EE + 255) / 256, 256>>>(dst);
        dis_kernel<<<nb, 256>>>();
        scan1_kernel<<<nb, 256>>>();
        scan2_kernel<<<1, 256>>>();
        scan3_kernel<<<nb, 256>>>();
        fill_kernel<<<(EE + 255) / 256, 256>>>(src, dst);
        gemm_tc_kernel<<<gemm_grid, 256, GEMM_SMEM>>>(x, Ws + 0 * FF * FF, bufT, NN);
    }

    // layer 0
    agg_elu_kernel<<<node_grid, 256>>>(bufT, bs + 0 * FF, bufH);
    // layer 1
    gemm_tc_kernel<<<gemm_grid, 256, GEMM_SMEM>>>(bufH, Ws + 1 * FF * FF, bufT, NN);
    agg_elu_kernel<<<node_grid, 256>>>(bufT, bs + 1 * FF, bufH);
    // layer 2 + fused head
    gemm_tc_kernel<<<gemm_grid, 256, GEMM_SMEM>>>(bufH, Ws + 2 * FF * FF, bufT, NN);
    agg_elu_head_kernel<<<node_grid, 256>>>(bufT, bs + 2 * FF, Wl, bl, out);
}